// round 3
// baseline (speedup 1.0000x reference)
#include <cuda_runtime.h>
#include <cuda_bf16.h>

// feature_maps: [1, 200, 304, 256] fp32 (NHWC) | proposals: [N,4] (x1,y1,x2,y2)
// image_shape: [2] int32 | output: [N, 7, 7, 256] fp32
#define HF   200
#define WF   304
#define CC   256
#define CROP 14
#define POOL 7

// Per-sample axis data, weights pre-folded with validity, indices pre-scaled
// to element offsets (y: i*WF*CC, x: i*CC).
struct __align__(16) Axis {
    int   o0;   // clipped floor index * stride
    int   o1;   // clipped (floor+1) index * stride
    float w0;   // (1-l) * valid
    float w1;   //   l   * valid
};

__device__ __forceinline__ float4 max4(float4 a, float4 b) {
    float4 r;
    r.x = fmaxf(a.x, b.x);
    r.y = fmaxf(a.y, b.y);
    r.z = fmaxf(a.z, b.z);
    r.w = fmaxf(a.w, b.w);
    return r;
}

// 4-corner weighted sum: v00*p00 + v01*p01 + v10*p10 + v11*p11 (per component)
__device__ __forceinline__ float4 dot4(float4 v00, float4 v01, float4 v10, float4 v11,
                                       float p00, float p01, float p10, float p11) {
    float4 r;
    r.x = fmaf(v11.x, p11, fmaf(v10.x, p10, fmaf(v01.x, p01, v00.x * p00)));
    r.y = fmaf(v11.y, p11, fmaf(v10.y, p10, fmaf(v01.y, p01, v00.y * p00)));
    r.z = fmaf(v11.z, p11, fmaf(v10.z, p10, fmaf(v01.z, p01, v00.z * p00)));
    r.w = fmaf(v11.w, p11, fmaf(v10.w, p10, fmaf(v01.w, p01, v00.w * p00)));
    return r;
}

__global__ __launch_bounds__(256, 4)
void roi_pool_kernel(const float* __restrict__ fm,
                     const float* __restrict__ props,
                     const int*   __restrict__ ishape,
                     float* __restrict__ out,
                     int N)
{
    __shared__ Axis sy[CROP];
    __shared__ Axis sx[CROP];

    const int n   = blockIdx.x;
    const int tx  = threadIdx.x;                    // 0..63: channel group (float4)
    const int ty  = threadIdx.y;                    // 0..3 : pooled-cell slice
    const int tid = ty * 64 + tx;

    // ---- Per-box axis parameters (28 threads, once per box) ----
    if (tid < 2 * CROP) {
        const float h = (float)ishape[0];
        const float w = (float)ishape[1];
        const float* p = props + (size_t)n * 4;
        const bool isY = (tid < CROP);
        const int  i   = isY ? tid : tid - CROP;
        const float c1 = isY ? (p[1] / h) : (p[0] / w);
        const float c2 = isY ? (p[3] / h) : (p[2] / w);
        const float D  = isY ? (float)(HF - 1) : (float)(WF - 1);
        const int   stride = isY ? (WF * CC) : CC;
        const float step = (c2 - c1) * D / (float)(CROP - 1);
        const float s    = fmaf((float)i, step, c1 * D);
        const float f    = floorf(s);
        int i0 = (int)f;
        i0 = max(0, min(i0, (int)D));
        const int i1 = min(i0 + 1, (int)D);
        const float l = s - f;
        const float v = (s >= 0.0f && s <= D) ? 1.0f : 0.0f;
        Axis a;
        a.o0 = i0 * stride;
        a.o1 = i1 * stride;
        a.w0 = (1.0f - l) * v;
        a.w1 = l * v;
        if (isY) sy[i] = a; else sx[i] = a;
    }
    __syncthreads();

    const float* fmc = fm + tx * 4;   // fold channel offset into the base pointer

    // ---- 49 pooled cells, strided over threadIdx.y ----
    for (int cell = ty; cell < POOL * POOL; cell += 4) {
        const int py = cell / POOL;
        const int px = cell - py * POOL;

        const Axis ax0 = sx[2 * px];
        const Axis ax1 = sx[2 * px + 1];

        float4 m = make_float4(-__FLT_MAX__, -__FLT_MAX__, -__FLT_MAX__, -__FLT_MAX__);

        #pragma unroll
        for (int dy = 0; dy < 2; ++dy) {
            const Axis ay = sy[2 * py + dy];
            const float* r0 = fmc + ay.o0;
            const float* r1 = fmc + ay.o1;

            // front-batch all 8 loads for this y-sample before any math
            const float4 a00 = *(const float4*)(r0 + ax0.o0);
            const float4 a01 = *(const float4*)(r0 + ax0.o1);
            const float4 a10 = *(const float4*)(r1 + ax0.o0);
            const float4 a11 = *(const float4*)(r1 + ax0.o1);
            const float4 b00 = *(const float4*)(r0 + ax1.o0);
            const float4 b01 = *(const float4*)(r0 + ax1.o1);
            const float4 b10 = *(const float4*)(r1 + ax1.o0);
            const float4 b11 = *(const float4*)(r1 + ax1.o1);

            // corner weights (scalar, 8 FMUL)
            const float pa00 = ay.w0 * ax0.w0;
            const float pa01 = ay.w0 * ax0.w1;
            const float pa10 = ay.w1 * ax0.w0;
            const float pa11 = ay.w1 * ax0.w1;
            const float pb00 = ay.w0 * ax1.w0;
            const float pb01 = ay.w0 * ax1.w1;
            const float pb10 = ay.w1 * ax1.w0;
            const float pb11 = ay.w1 * ax1.w1;

            m = max4(m, dot4(a00, a01, a10, a11, pa00, pa01, pa10, pa11));
            m = max4(m, dot4(b00, b01, b10, b11, pb00, pb01, pb10, pb11));
        }

        float* o = out + (((size_t)n * (POOL * POOL)) + cell) * CC + tx * 4;
        __stcs((float4*)o, m);   // streaming store: keep the feature map in L2
    }
}

extern "C" void kernel_launch(void* const* d_in, const int* in_sizes, int n_in,
                              void* d_out, int out_size) {
    const float* fm     = (const float*)d_in[0];
    const float* props  = (const float*)d_in[1];
    const int*   ishape = (const int*)  d_in[2];
    float*       out    = (float*)d_out;

    const int N = in_sizes[1] / 4;   // proposals: [N, 4]

    dim3 block(64, 4, 1);
    dim3 grid(N, 1, 1);
    roi_pool_kernel<<<grid, block>>>(fm, props, ishape, out, N);
}